// round 16
// baseline (speedup 1.0000x reference)
#include <cuda_runtime.h>
#include <cuda_fp16.h>
#include <cstdint>

#define BNUM   4
#define SEQ    512
#define DMODEL 1024
#define HDIM   256
#define MTOT   2048
#define KP2    256       // stage-2 K (pure fp16)
#define NJC    1024      // SEQ * 2 (j,c interleaved)

// Scratch (allocation-free __device__ globals)
__device__ __align__(16) __half g_Xp[MTOT * DMODEL];         // 4 MB
__device__ __align__(16) __half g_W1p[HDIM * DMODEL];        // 0.5 MB
__device__ __align__(16) __half g_Ap[MTOT * KP2];            // 1 MB
__device__ __align__(16) __half g_Bp[BNUM * NJC * KP2];      // 2 MB

// ---------------------------------------------------------------------------
// helpers
// ---------------------------------------------------------------------------
static __device__ __forceinline__ uint32_t smem_u32(const void* p) {
    uint32_t a;
    asm("{ .reg .u64 t; cvta.to.shared.u64 t, %1; cvt.u32.u64 %0, t; }"
        : "=r"(a) : "l"(p));
    return a;
}
static __device__ __forceinline__ void cp_async16(uint32_t saddr, const void* gaddr) {
    asm volatile("cp.async.cg.shared.global [%0], [%1], 16;"
                 :: "r"(saddr), "l"(gaddr) : "memory");
}
static __device__ __forceinline__ void cp_commit() {
    asm volatile("cp.async.commit_group;" ::: "memory");
}
static __device__ __forceinline__ void cp_wait1() {
    asm volatile("cp.async.wait_group 1;" ::: "memory");
}
static __device__ __forceinline__ void cp_wait0() {
    asm volatile("cp.async.wait_group 0;" ::: "memory");
}
static __device__ __forceinline__ void ldsm_x4(uint32_t* r, uint32_t addr) {
    asm volatile("ldmatrix.sync.aligned.m8n8.x4.shared.b16 {%0,%1,%2,%3}, [%4];"
                 : "=r"(r[0]), "=r"(r[1]), "=r"(r[2]), "=r"(r[3]) : "r"(addr));
}
static __device__ __forceinline__ void mma16816(float* d, const uint32_t* a,
                                                uint32_t b0, uint32_t b1) {
    asm volatile(
        "mma.sync.aligned.m16n8k16.row.col.f32.f16.f16.f32 "
        "{%0,%1,%2,%3}, {%4,%5,%6,%7}, {%8,%9}, {%0,%1,%2,%3};"
        : "+f"(d[0]), "+f"(d[1]), "+f"(d[2]), "+f"(d[3])
        : "r"(a[0]), "r"(a[1]), "r"(a[2]), "r"(a[3]), "r"(b0), "r"(b1));
}
static __device__ __forceinline__ void st_h2f(__half* p, float a, float b) {
    __half2 t = __floats2half2_rn(a, b);
    *(__half2*)p = t;
}
static __device__ __forceinline__ uint32_t pack_h2(float a, float b) {
    __half2 h = __floats2half2_rn(a, b);
    return *(uint32_t*)&h;
}

// ---------------------------------------------------------------------------
// Prep 1: fp32 -> fp16 convert of X and W1. 16 floats per thread via 4
// independent float4 loads (MLP=4), 2 uint4 stores.
// ---------------------------------------------------------------------------
#define NX16 (MTOT * DMODEL / 16)    // 131072 thread-chunks for X
#define NW16 (HDIM * DMODEL / 16)    // 16384 thread-chunks for W1

__global__ __launch_bounds__(256) void split_xw(const float* __restrict__ X,
                                                const float* __restrict__ W1) {
    int idx = blockIdx.x * 256 + threadIdx.x;
    const float* src;
    __half* dst;
    if (idx < NX16) {
        src = X + (size_t)idx * 16;
        dst = g_Xp + (size_t)idx * 16;
    } else {
        int i2 = idx - NX16;
        if (i2 >= NW16) return;
        src = W1 + (size_t)i2 * 16;
        dst = g_W1p + (size_t)i2 * 16;
    }
    float4 v0 = *(const float4*)(src);
    float4 v1 = *(const float4*)(src + 4);
    float4 v2 = *(const float4*)(src + 8);
    float4 v3 = *(const float4*)(src + 12);
    uint4 o0, o1;
    o0.x = pack_h2(v0.x, v0.y); o0.y = pack_h2(v0.z, v0.w);
    o0.z = pack_h2(v1.x, v1.y); o0.w = pack_h2(v1.z, v1.w);
    o1.x = pack_h2(v2.x, v2.y); o1.y = pack_h2(v2.z, v2.w);
    o1.z = pack_h2(v3.x, v3.y); o1.w = pack_h2(v3.z, v3.w);
    *(uint4*)(dst)     = o0;
    *(uint4*)(dst + 8) = o1;
}

// ---------------------------------------------------------------------------
// common tiling constants
// ---------------------------------------------------------------------------
#define BK   64
#define ASB  8192                     // stage bytes (A or B): 64 rows * 128B
#define BOFFB (3 * ASB)               // B region offset: 24576
#define SMEM_SZ (6 * ASB)             // 49152 bytes == default 48KB limit
#define SDP  66                       // fp32 combine-tile pitch

// ---------------------------------------------------------------------------
// GEMM 1 (full K, fused epilogue): o[m, n0+..] = X[m,:] @ W1[n,:]^T + b1;
// writes g_Ap = h(o) and g_Bp rows 2j+c = h(o * w_c). Grid (4, 32), NC=16.
// 256 thr / 8 warps, in-CTA k16-split (grp), full-tile smem combine.
// ---------------------------------------------------------------------------
__global__ __launch_bounds__(256, 4) void gemm1_kernel(const float* __restrict__ W2,
                                                       const float* __restrict__ b1) {
    extern __shared__ char smem[];
    const uint32_t sbase = smem_u32(smem);
    const int tid = threadIdx.x;
    const int wid = tid >> 5, lane = tid & 31;
    const int grp = wid >> 2;
    const int wm = wid & 1, wn = (wid >> 1) & 1;
    const int m0 = blockIdx.y * 64, n0 = blockIdx.x * 64;

    const __half* Ab = g_Xp + (size_t)m0 * DMODEL;
    const __half* Bb = g_W1p + (size_t)n0 * DMODEL;
    const int nc = DMODEL / BK;                      // 16

    const int lrow = tid >> 2;
    const int lcb  = (tid & 3) * 2;
    const int lxr  = lrow & 7;

    float acc[2][4][4];
#pragma unroll
    for (int mt = 0; mt < 2; ++mt)
#pragma unroll
        for (int j = 0; j < 4; ++j)
#pragma unroll
            for (int e = 0; e < 4; ++e) acc[mt][j][e] = 0.0f;

#pragma unroll
    for (int s = 0; s < 2; ++s) {
        const __half* Ag = Ab + s * BK + (size_t)lrow * DMODEL + lcb * 8;
        const __half* Bg = Bb + s * BK + (size_t)lrow * DMODEL + lcb * 8;
        const uint32_t rowA = sbase + s * ASB + lrow * 128;
        const uint32_t rowB = rowA + BOFFB;
#pragma unroll
        for (int q = 0; q < 2; ++q) {
            const uint32_t sw = (uint32_t)(((lcb + q) ^ lxr) << 4);
            cp_async16(rowA + sw, Ag + q * 8);
            cp_async16(rowB + sw, Bg + q * 8);
        }
        cp_commit();
    }

    const int arow = wm * 32 + (lane & 15);
    const int brow = wn * 32 + (lane & 15);
    const int kl   = lane >> 4;
    const uint32_t aRow = sbase + (uint32_t)(arow * 128);
    const uint32_t bRow = sbase + BOFFB + (uint32_t)(brow * 128);
    const int axr = arow & 7, bxr = brow & 7;

    for (int kc = 0; kc < nc; ++kc) {
        cp_wait1();
        __syncthreads();

        const int s = kc % 3;
        const uint32_t aS = aRow + (uint32_t)(s * ASB);
        const uint32_t bS = bRow + (uint32_t)(s * ASB);
#pragma unroll
        for (int ksi = 0; ksi < 2; ++ksi) {
            const int c16 = (grp * 2 + ksi) * 2 + kl;
            const uint32_t swa = (uint32_t)((c16 ^ axr) << 4);
            const uint32_t swb = (uint32_t)((c16 ^ bxr) << 4);
            uint32_t a0[4], a1[4], b0[4], b1r[4];
            ldsm_x4(a0, aS + swa);
            ldsm_x4(a1, aS + 16 * 128 + swa);
            ldsm_x4(b0, bS + swb);
            ldsm_x4(b1r, bS + 16 * 128 + swb);
            mma16816(acc[0][0], a0, b0[0], b0[2]);
            mma16816(acc[0][1], a0, b0[1], b0[3]);
            mma16816(acc[0][2], a0, b1r[0], b1r[2]);
            mma16816(acc[0][3], a0, b1r[1], b1r[3]);
            mma16816(acc[1][0], a1, b0[0], b0[2]);
            mma16816(acc[1][1], a1, b0[1], b0[3]);
            mma16816(acc[1][2], a1, b1r[0], b1r[2]);
            mma16816(acc[1][3], a1, b1r[1], b1r[3]);
        }

        if (kc + 2 < nc) {
            const int s2 = (kc + 2) % 3;
            const __half* Ag = Ab + (kc + 2) * BK + (size_t)lrow * DMODEL + lcb * 8;
            const __half* Bg = Bb + (kc + 2) * BK + (size_t)lrow * DMODEL + lcb * 8;
            const uint32_t rowA = sbase + s2 * ASB + lrow * 128;
            const uint32_t rowB = rowA + BOFFB;
#pragma unroll
            for (int q = 0; q < 2; ++q) {
                const uint32_t sw = (uint32_t)(((lcb + q) ^ lxr) << 4);
                cp_async16(rowA + sw, Ag + q * 8);
                cp_async16(rowB + sw, Bg + q * 8);
            }
        }
        cp_commit();
    }

    // combine both k-groups into full fp32 tile in smem
    cp_wait0();
    __syncthreads();
    float* sC = (float*)smem;
    const int rr = lane >> 2;
    const int cc0 = wn * 32 + (lane & 3) * 2;

    if (grp == 1) {
#pragma unroll
        for (int mt = 0; mt < 2; ++mt)
#pragma unroll
            for (int j = 0; j < 4; ++j) {
                const int r0 = wm * 32 + rr + mt * 16;
                const int c  = cc0 + j * 8;
                float2 v0; v0.x = acc[mt][j][0]; v0.y = acc[mt][j][1];
                float2 v1; v1.x = acc[mt][j][2]; v1.y = acc[mt][j][3];
                *(float2*)(sC + r0 * SDP + c)       = v0;
                *(float2*)(sC + (r0 + 8) * SDP + c) = v1;
            }
    }
    __syncthreads();
    if (grp == 0) {
#pragma unroll
        for (int mt = 0; mt < 2; ++mt)
#pragma unroll
            for (int j = 0; j < 4; ++j) {
                const int r0 = wm * 32 + rr + mt * 16;
                const int c  = cc0 + j * 8;
                float2 p0 = *(float2*)(sC + r0 * SDP + c);
                float2 p1 = *(float2*)(sC + (r0 + 8) * SDP + c);
                p0.x += acc[mt][j][0]; p0.y += acc[mt][j][1];
                p1.x += acc[mt][j][2]; p1.y += acc[mt][j][3];
                *(float2*)(sC + r0 * SDP + c)       = p0;
                *(float2*)(sC + (r0 + 8) * SDP + c) = p1;
            }
    }
    __syncthreads();

    // fused epilogue: o = sC + b1; write g_Ap (fp16) and g_Bp rows (o*w0, o*w1)
    {
        const int r  = tid >> 2;                     // 0..63
        const int cb = (tid & 3) * 16;               // 16 cols each
        const int m  = m0 + r;
        const int b  = m >> 9, j = m & 511;
        __half* ap  = g_Ap + (size_t)m * KP2 + n0;
        __half* bp0 = g_Bp + ((size_t)b * NJC + 2 * j) * KP2 + n0;
        __half* bp1 = bp0 + KP2;
#pragma unroll
        for (int e = 0; e < 8; ++e) {
            const int col = cb + e * 2;
            const float o0 = sC[r * SDP + col]     + b1[n0 + col];
            const float o1 = sC[r * SDP + col + 1] + b1[n0 + col + 1];
            const float w00 = W2[n0 + col],        w01 = W2[n0 + col + 1];
            const float w10 = W2[HDIM + n0 + col], w11 = W2[HDIM + n0 + col + 1];
            st_h2f(ap  + col, o0,       o1);
            st_h2f(bp0 + col, o0 * w00, o1 * w01);
            st_h2f(bp1 + col, o0 * w10, o1 * w11);
        }
    }
}

// ---------------------------------------------------------------------------
// GEMM 2: mma.sync fp16 TN, D[64,64], BK=64, NC=4, 3-stage cp.async pipeline,
// TRIANGULAR grid (2, 36, 4); off-diagonal pairs also write mirrored tile.
// ---------------------------------------------------------------------------
#define G2_NC (KP2 / BK)              // 4

__global__ __launch_bounds__(256, 4) void gemm2_kernel(const float* __restrict__ bias,
                                                       float* __restrict__ outp) {
    extern __shared__ char smem[];
    const uint32_t sbase = smem_u32(smem);
    const int tid = threadIdx.x;
    const int wid = tid >> 5, lane = tid & 31;
    const int grp = wid >> 2;
    const int wm = wid & 1, wn = (wid >> 1) & 1;
    const int bz = blockIdx.z;

    const int half = blockIdx.x;
    int p = blockIdx.y;
    int jt = 0;
    while (((jt + 1) * (jt + 2) >> 1) <= p) ++jt;
    const int it = p - ((jt * (jt + 1)) >> 1);
    const int m0 = it * 64;
    const int n0 = jt * 128 + half * 64;

    const __half* Ab = g_Ap + ((size_t)(bz * SEQ + m0)) * KP2;
    const __half* Bb = g_Bp + ((size_t)(bz * NJC + n0)) * KP2;

    const int lrow = tid >> 2;
    const int lcb  = (tid & 3) * 2;
    const int lxr  = lrow & 7;

    float acc[2][4][4];
#pragma unroll
    for (int mt = 0; mt < 2; ++mt)
#pragma unroll
        for (int j = 0; j < 4; ++j)
#pragma unroll
            for (int e = 0; e < 4; ++e) acc[mt][j][e] = 0.0f;

#pragma unroll
    for (int s = 0; s < 2; ++s) {
        const __half* Ag = Ab + s * BK + (size_t)lrow * KP2 + lcb * 8;
        const __half* Bg = Bb + s * BK + (size_t)lrow * KP2 + lcb * 8;
        const uint32_t rowA = sbase + s * ASB + lrow * 128;
        const uint32_t rowB = rowA + BOFFB;
#pragma unroll
        for (int q = 0; q < 2; ++q) {
            const uint32_t sw = (uint32_t)(((lcb + q) ^ lxr) << 4);
            cp_async16(rowA + sw, Ag + q * 8);
            cp_async16(rowB + sw, Bg + q * 8);
        }
        cp_commit();
    }

    const int arow = wm * 32 + (lane & 15);
    const int brow = wn * 32 + (lane & 15);
    const int kl   = lane >> 4;
    const uint32_t aRow = sbase + (uint32_t)(arow * 128);
    const uint32_t bRow = sbase + BOFFB + (uint32_t)(brow * 128);
    const int axr = arow & 7, bxr = brow & 7;

    for (int kc = 0; kc < G2_NC; ++kc) {
        cp_wait1();
        __syncthreads();

        const int s = kc % 3;
        const uint32_t aS = aRow + (uint32_t)(s * ASB);
        const uint32_t bS = bRow + (uint32_t)(s * ASB);
#pragma unroll
        for (int ksi = 0; ksi < 2; ++ksi) {
            const int c16 = (grp * 2 + ksi) * 2 + kl;
            const uint32_t swa = (uint32_t)((c16 ^ axr) << 4);
            const uint32_t swb = (uint32_t)((c16 ^ bxr) << 4);
            uint32_t a0[4], a1[4], b0[4], b1[4];
            ldsm_x4(a0, aS + swa);
            ldsm_x4(a1, aS + 16 * 128 + swa);
            ldsm_x4(b0, bS + swb);
            ldsm_x4(b1, bS + 16 * 128 + swb);
            mma16816(acc[0][0], a0, b0[0], b0[2]);
            mma16816(acc[0][1], a0, b0[1], b0[3]);
            mma16816(acc[0][2], a0, b1[0], b1[2]);
            mma16816(acc[0][3], a0, b1[1], b1[3]);
            mma16816(acc[1][0], a1, b0[0], b0[2]);
            mma16816(acc[1][1], a1, b0[1], b0[3]);
            mma16816(acc[1][2], a1, b1[0], b1[2]);
            mma16816(acc[1][3], a1, b1[1], b1[3]);
        }

        if (kc + 2 < G2_NC) {
            const int s2 = (kc + 2) % 3;
            const __half* Ag = Ab + (kc + 2) * BK + (size_t)lrow * KP2 + lcb * 8;
            const __half* Bg = Bb + (kc + 2) * BK + (size_t)lrow * KP2 + lcb * 8;
            const uint32_t rowA = sbase + s2 * ASB + lrow * 128;
            const uint32_t rowB = rowA + BOFFB;
#pragma unroll
            for (int q = 0; q < 2; ++q) {
                const uint32_t sw = (uint32_t)(((lcb + q) ^ lxr) << 4);
                cp_async16(rowA + sw, Ag + q * 8);
                cp_async16(rowB + sw, Bg + q * 8);
            }
        }
        cp_commit();
    }

    cp_wait0();
    __syncthreads();

    float* sC = (float*)smem;
    const int rr = lane >> 2;
    const int cc0 = wn * 32 + (lane & 3) * 2;

    if (grp == 1) {
#pragma unroll
        for (int mt = 0; mt < 2; ++mt)
#pragma unroll
            for (int j = 0; j < 4; ++j) {
                const int r0 = wm * 32 + rr + mt * 16;
                const int c  = cc0 + j * 8;
                float2 v0; v0.x = acc[mt][j][0]; v0.y = acc[mt][j][1];
                float2 v1; v1.x = acc[mt][j][2]; v1.y = acc[mt][j][3];
                *(float2*)(sC + r0 * SDP + c)       = v0;
                *(float2*)(sC + (r0 + 8) * SDP + c) = v1;
            }
    }
    __syncthreads();
    if (grp == 0) {
#pragma unroll
        for (int mt = 0; mt < 2; ++mt)
#pragma unroll
            for (int j = 0; j < 4; ++j) {
                const int r0 = wm * 32 + rr + mt * 16;
                const int c  = cc0 + j * 8;
                float2 p0 = *(float2*)(sC + r0 * SDP + c);
                float2 p1 = *(float2*)(sC + (r0 + 8) * SDP + c);
                p0.x += acc[mt][j][0]; p0.y += acc[mt][j][1];
                p1.x += acc[mt][j][2]; p1.y += acc[mt][j][3];
                *(float2*)(sC + r0 * SDP + c)       = p0;
                *(float2*)(sC + (r0 + 8) * SDP + c) = p1;
            }
    }
    __syncthreads();

    const float bv0 = bias[0], bv1 = bias[1];
    {
        const int r  = tid >> 2;
        const int cb = (tid & 3) * 16;
        float* dbase = outp + ((size_t)(bz * SEQ + m0 + r)) * NJC + n0;
#pragma unroll
        for (int e = 0; e < 8; ++e) {
            const int col = cb + e * 2;
            float2 v;
            v.x = sC[r * SDP + col] + bv0;
            v.y = sC[r * SDP + col + 1] + bv1;
            *(float2*)(dbase + col) = v;
        }
    }
    if (it != jt) {
        const int jl = tid >> 3;
        const int ql = tid & 7;
        const int j  = jt * 64 + half * 32 + jl;
        float* mbase = outp + ((size_t)(bz * SEQ + j)) * NJC + 2 * m0;
#pragma unroll
        for (int e = 0; e < 8; ++e) {
            const int q = ql + 8 * e;
            float2 s = *(float2*)(sC + q * SDP + 2 * jl);
            float2 v;
            v.x = s.x + bv0;
            v.y = s.y + bv1;
            *(float2*)(mbase + 2 * q) = v;
        }
    }
}

// ---------------------------------------------------------------------------
extern "C" void kernel_launch(void* const* d_in, const int* in_sizes, int n_in,
                              void* d_out, int out_size)
{
    const float* x  = (const float*)d_in[0];   // [4, 512, 1024]
    const float* W1 = (const float*)d_in[1];   // [256, 1024]
    const float* b1 = (const float*)d_in[2];   // [256]
    const float* W2 = (const float*)d_in[3];   // [2, 256]
    const float* b2 = (const float*)d_in[4];   // [2]
    float* out = (float*)d_out;                // [4, 512, 512, 2]

    // Prep: fp32 -> fp16 convert (16 floats/thread, MLP=4)
    split_xw<<<(NX16 + NW16) / 256, 256>>>(x, W1);

    // Stage 1 GEMM (full K=1024, fused o/A'/B' epilogue): grid 128 CTAs
    gemm1_kernel<<<dim3(HDIM / 64, MTOT / 64), 256, SMEM_SZ>>>(W2, b1);

    // Stage 2 GEMM (triangular): 36 pairs x 2 jc-halves x 4 batches = 288 CTAs
    gemm2_kernel<<<dim3(2, 36, BNUM), 256, SMEM_SZ>>>(b2, out);
}

// round 17
// speedup vs baseline: 1.0972x; 1.0972x over previous
#include <cuda_runtime.h>
#include <cuda_fp16.h>
#include <cstdint>

#define BNUM   4
#define SEQ    512
#define DMODEL 1024
#define HDIM   256
#define MTOT   2048
#define KP2    256       // stage-2 K (pure fp16)
#define NJC    1024      // SEQ * 2 (j,c interleaved)

// Scratch (allocation-free __device__ globals)
__device__ __align__(16) __half g_Xp[MTOT * DMODEL];         // 4 MB
__device__ __align__(16) __half g_W1p[HDIM * DMODEL];        // 0.5 MB
__device__ __align__(16) __half g_Ap[MTOT * KP2];            // 1 MB
__device__ __align__(16) __half g_Bp[BNUM * NJC * KP2];      // 2 MB

// ---------------------------------------------------------------------------
// helpers
// ---------------------------------------------------------------------------
static __device__ __forceinline__ uint32_t smem_u32(const void* p) {
    uint32_t a;
    asm("{ .reg .u64 t; cvta.to.shared.u64 t, %1; cvt.u32.u64 %0, t; }"
        : "=r"(a) : "l"(p));
    return a;
}
static __device__ __forceinline__ void cp_async16(uint32_t saddr, const void* gaddr) {
    asm volatile("cp.async.cg.shared.global [%0], [%1], 16;"
                 :: "r"(saddr), "l"(gaddr) : "memory");
}
static __device__ __forceinline__ void cp_commit() {
    asm volatile("cp.async.commit_group;" ::: "memory");
}
static __device__ __forceinline__ void cp_wait1() {
    asm volatile("cp.async.wait_group 1;" ::: "memory");
}
static __device__ __forceinline__ void cp_wait0() {
    asm volatile("cp.async.wait_group 0;" ::: "memory");
}
static __device__ __forceinline__ void ldsm_x4(uint32_t* r, uint32_t addr) {
    asm volatile("ldmatrix.sync.aligned.m8n8.x4.shared.b16 {%0,%1,%2,%3}, [%4];"
                 : "=r"(r[0]), "=r"(r[1]), "=r"(r[2]), "=r"(r[3]) : "r"(addr));
}
static __device__ __forceinline__ void mma16816(float* d, const uint32_t* a,
                                                uint32_t b0, uint32_t b1) {
    asm volatile(
        "mma.sync.aligned.m16n8k16.row.col.f32.f16.f16.f32 "
        "{%0,%1,%2,%3}, {%4,%5,%6,%7}, {%8,%9}, {%0,%1,%2,%3};"
        : "+f"(d[0]), "+f"(d[1]), "+f"(d[2]), "+f"(d[3])
        : "r"(a[0]), "r"(a[1]), "r"(a[2]), "r"(a[3]), "r"(b0), "r"(b1));
}
static __device__ __forceinline__ void st_h2f(__half* p, float a, float b) {
    __half2 t = __floats2half2_rn(a, b);
    *(__half2*)p = t;
}
static __device__ __forceinline__ uint32_t pack_h2(float a, float b) {
    __half2 h = __floats2half2_rn(a, b);
    return *(uint32_t*)&h;
}

// ---------------------------------------------------------------------------
// Prep 1: fp32 -> fp16 convert of X and W1. 8 floats per thread via 2
// independent float4 loads (MLP=2), 1 uint4 (16B) store. High occupancy.
// ---------------------------------------------------------------------------
#define NX8 (MTOT * DMODEL / 8)      // 262144 thread-chunks for X
#define NW8 (HDIM * DMODEL / 8)      // 32768 thread-chunks for W1

__global__ __launch_bounds__(256) void split_xw(const float* __restrict__ X,
                                                const float* __restrict__ W1) {
    int idx = blockIdx.x * 256 + threadIdx.x;
    const float* src;
    __half* dst;
    if (idx < NX8) {
        src = X + (size_t)idx * 8;
        dst = g_Xp + (size_t)idx * 8;
    } else {
        int i2 = idx - NX8;
        if (i2 >= NW8) return;
        src = W1 + (size_t)i2 * 8;
        dst = g_W1p + (size_t)i2 * 8;
    }
    float4 v0 = *(const float4*)(src);
    float4 v1 = *(const float4*)(src + 4);
    uint4 o;
    o.x = pack_h2(v0.x, v0.y); o.y = pack_h2(v0.z, v0.w);
    o.z = pack_h2(v1.x, v1.y); o.w = pack_h2(v1.z, v1.w);
    *(uint4*)(dst) = o;
}

// ---------------------------------------------------------------------------
// common tiling constants
// ---------------------------------------------------------------------------
#define BK   64
#define ASB  8192                     // stage bytes (A or B): 64 rows * 128B
#define BOFFB (3 * ASB)               // B region offset: 24576
#define SMEM_SZ (6 * ASB)             // 49152 bytes == default 48KB limit
#define SDP  66                       // fp32 combine-tile pitch

// ---------------------------------------------------------------------------
// GEMM 1 (full K, fused epilogue): o[m, n0+..] = X[m,:] @ W1[n,:]^T + b1;
// writes g_Ap = h(o) and g_Bp rows 2j+c = h(o * w_c). Grid (4, 32), NC=16.
// 256 thr / 8 warps, in-CTA k16-split (grp), full-tile smem combine.
// ---------------------------------------------------------------------------
__global__ __launch_bounds__(256, 4) void gemm1_kernel(const float* __restrict__ W2,
                                                       const float* __restrict__ b1) {
    extern __shared__ char smem[];
    const uint32_t sbase = smem_u32(smem);
    const int tid = threadIdx.x;
    const int wid = tid >> 5, lane = tid & 31;
    const int grp = wid >> 2;
    const int wm = wid & 1, wn = (wid >> 1) & 1;
    const int m0 = blockIdx.y * 64, n0 = blockIdx.x * 64;

    const __half* Ab = g_Xp + (size_t)m0 * DMODEL;
    const __half* Bb = g_W1p + (size_t)n0 * DMODEL;
    const int nc = DMODEL / BK;                      // 16

    const int lrow = tid >> 2;
    const int lcb  = (tid & 3) * 2;
    const int lxr  = lrow & 7;

    float acc[2][4][4];
#pragma unroll
    for (int mt = 0; mt < 2; ++mt)
#pragma unroll
        for (int j = 0; j < 4; ++j)
#pragma unroll
            for (int e = 0; e < 4; ++e) acc[mt][j][e] = 0.0f;

#pragma unroll
    for (int s = 0; s < 2; ++s) {
        const __half* Ag = Ab + s * BK + (size_t)lrow * DMODEL + lcb * 8;
        const __half* Bg = Bb + s * BK + (size_t)lrow * DMODEL + lcb * 8;
        const uint32_t rowA = sbase + s * ASB + lrow * 128;
        const uint32_t rowB = rowA + BOFFB;
#pragma unroll
        for (int q = 0; q < 2; ++q) {
            const uint32_t sw = (uint32_t)(((lcb + q) ^ lxr) << 4);
            cp_async16(rowA + sw, Ag + q * 8);
            cp_async16(rowB + sw, Bg + q * 8);
        }
        cp_commit();
    }

    const int arow = wm * 32 + (lane & 15);
    const int brow = wn * 32 + (lane & 15);
    const int kl   = lane >> 4;
    const uint32_t aRow = sbase + (uint32_t)(arow * 128);
    const uint32_t bRow = sbase + BOFFB + (uint32_t)(brow * 128);
    const int axr = arow & 7, bxr = brow & 7;

    for (int kc = 0; kc < nc; ++kc) {
        cp_wait1();
        __syncthreads();

        const int s = kc % 3;
        const uint32_t aS = aRow + (uint32_t)(s * ASB);
        const uint32_t bS = bRow + (uint32_t)(s * ASB);
#pragma unroll
        for (int ksi = 0; ksi < 2; ++ksi) {
            const int c16 = (grp * 2 + ksi) * 2 + kl;
            const uint32_t swa = (uint32_t)((c16 ^ axr) << 4);
            const uint32_t swb = (uint32_t)((c16 ^ bxr) << 4);
            uint32_t a0[4], a1[4], b0[4], b1r[4];
            ldsm_x4(a0, aS + swa);
            ldsm_x4(a1, aS + 16 * 128 + swa);
            ldsm_x4(b0, bS + swb);
            ldsm_x4(b1r, bS + 16 * 128 + swb);
            mma16816(acc[0][0], a0, b0[0], b0[2]);
            mma16816(acc[0][1], a0, b0[1], b0[3]);
            mma16816(acc[0][2], a0, b1r[0], b1r[2]);
            mma16816(acc[0][3], a0, b1r[1], b1r[3]);
            mma16816(acc[1][0], a1, b0[0], b0[2]);
            mma16816(acc[1][1], a1, b0[1], b0[3]);
            mma16816(acc[1][2], a1, b1r[0], b1r[2]);
            mma16816(acc[1][3], a1, b1r[1], b1r[3]);
        }

        if (kc + 2 < nc) {
            const int s2 = (kc + 2) % 3;
            const __half* Ag = Ab + (kc + 2) * BK + (size_t)lrow * DMODEL + lcb * 8;
            const __half* Bg = Bb + (kc + 2) * BK + (size_t)lrow * DMODEL + lcb * 8;
            const uint32_t rowA = sbase + s2 * ASB + lrow * 128;
            const uint32_t rowB = rowA + BOFFB;
#pragma unroll
            for (int q = 0; q < 2; ++q) {
                const uint32_t sw = (uint32_t)(((lcb + q) ^ lxr) << 4);
                cp_async16(rowA + sw, Ag + q * 8);
                cp_async16(rowB + sw, Bg + q * 8);
            }
        }
        cp_commit();
    }

    // combine both k-groups into full fp32 tile in smem
    cp_wait0();
    __syncthreads();
    float* sC = (float*)smem;
    const int rr = lane >> 2;
    const int cc0 = wn * 32 + (lane & 3) * 2;

    if (grp == 1) {
#pragma unroll
        for (int mt = 0; mt < 2; ++mt)
#pragma unroll
            for (int j = 0; j < 4; ++j) {
                const int r0 = wm * 32 + rr + mt * 16;
                const int c  = cc0 + j * 8;
                float2 v0; v0.x = acc[mt][j][0]; v0.y = acc[mt][j][1];
                float2 v1; v1.x = acc[mt][j][2]; v1.y = acc[mt][j][3];
                *(float2*)(sC + r0 * SDP + c)       = v0;
                *(float2*)(sC + (r0 + 8) * SDP + c) = v1;
            }
    }
    __syncthreads();
    if (grp == 0) {
#pragma unroll
        for (int mt = 0; mt < 2; ++mt)
#pragma unroll
            for (int j = 0; j < 4; ++j) {
                const int r0 = wm * 32 + rr + mt * 16;
                const int c  = cc0 + j * 8;
                float2 p0 = *(float2*)(sC + r0 * SDP + c);
                float2 p1 = *(float2*)(sC + (r0 + 8) * SDP + c);
                p0.x += acc[mt][j][0]; p0.y += acc[mt][j][1];
                p1.x += acc[mt][j][2]; p1.y += acc[mt][j][3];
                *(float2*)(sC + r0 * SDP + c)       = p0;
                *(float2*)(sC + (r0 + 8) * SDP + c) = p1;
            }
    }
    __syncthreads();

    // fused epilogue: o = sC + b1; write g_Ap (fp16) and g_Bp rows (o*w0, o*w1)
    {
        const int r  = tid >> 2;                     // 0..63
        const int cb = (tid & 3) * 16;               // 16 cols each
        const int m  = m0 + r;
        const int b  = m >> 9, j = m & 511;
        __half* ap  = g_Ap + (size_t)m * KP2 + n0;
        __half* bp0 = g_Bp + ((size_t)b * NJC + 2 * j) * KP2 + n0;
        __half* bp1 = bp0 + KP2;
#pragma unroll
        for (int e = 0; e < 8; ++e) {
            const int col = cb + e * 2;
            const float o0 = sC[r * SDP + col]     + b1[n0 + col];
            const float o1 = sC[r * SDP + col + 1] + b1[n0 + col + 1];
            const float w00 = W2[n0 + col],        w01 = W2[n0 + col + 1];
            const float w10 = W2[HDIM + n0 + col], w11 = W2[HDIM + n0 + col + 1];
            st_h2f(ap  + col, o0,       o1);
            st_h2f(bp0 + col, o0 * w00, o1 * w01);
            st_h2f(bp1 + col, o0 * w10, o1 * w11);
        }
    }
}

// ---------------------------------------------------------------------------
// GEMM 2: mma.sync fp16 TN, D[64,64], BK=64, NC=4, 3-stage cp.async pipeline,
// TRIANGULAR grid (2, 36, 4); off-diagonal pairs also write mirrored tile.
// ---------------------------------------------------------------------------
#define G2_NC (KP2 / BK)              // 4

__global__ __launch_bounds__(256, 4) void gemm2_kernel(const float* __restrict__ bias,
                                                       float* __restrict__ outp) {
    extern __shared__ char smem[];
    const uint32_t sbase = smem_u32(smem);
    const int tid = threadIdx.x;
    const int wid = tid >> 5, lane = tid & 31;
    const int grp = wid >> 2;
    const int wm = wid & 1, wn = (wid >> 1) & 1;
    const int bz = blockIdx.z;

    const int half = blockIdx.x;
    int p = blockIdx.y;
    int jt = 0;
    while (((jt + 1) * (jt + 2) >> 1) <= p) ++jt;
    const int it = p - ((jt * (jt + 1)) >> 1);
    const int m0 = it * 64;
    const int n0 = jt * 128 + half * 64;

    const __half* Ab = g_Ap + ((size_t)(bz * SEQ + m0)) * KP2;
    const __half* Bb = g_Bp + ((size_t)(bz * NJC + n0)) * KP2;

    const int lrow = tid >> 2;
    const int lcb  = (tid & 3) * 2;
    const int lxr  = lrow & 7;

    float acc[2][4][4];
#pragma unroll
    for (int mt = 0; mt < 2; ++mt)
#pragma unroll
        for (int j = 0; j < 4; ++j)
#pragma unroll
            for (int e = 0; e < 4; ++e) acc[mt][j][e] = 0.0f;

#pragma unroll
    for (int s = 0; s < 2; ++s) {
        const __half* Ag = Ab + s * BK + (size_t)lrow * KP2 + lcb * 8;
        const __half* Bg = Bb + s * BK + (size_t)lrow * KP2 + lcb * 8;
        const uint32_t rowA = sbase + s * ASB + lrow * 128;
        const uint32_t rowB = rowA + BOFFB;
#pragma unroll
        for (int q = 0; q < 2; ++q) {
            const uint32_t sw = (uint32_t)(((lcb + q) ^ lxr) << 4);
            cp_async16(rowA + sw, Ag + q * 8);
            cp_async16(rowB + sw, Bg + q * 8);
        }
        cp_commit();
    }

    const int arow = wm * 32 + (lane & 15);
    const int brow = wn * 32 + (lane & 15);
    const int kl   = lane >> 4;
    const uint32_t aRow = sbase + (uint32_t)(arow * 128);
    const uint32_t bRow = sbase + BOFFB + (uint32_t)(brow * 128);
    const int axr = arow & 7, bxr = brow & 7;

    for (int kc = 0; kc < G2_NC; ++kc) {
        cp_wait1();
        __syncthreads();

        const int s = kc % 3;
        const uint32_t aS = aRow + (uint32_t)(s * ASB);
        const uint32_t bS = bRow + (uint32_t)(s * ASB);
#pragma unroll
        for (int ksi = 0; ksi < 2; ++ksi) {
            const int c16 = (grp * 2 + ksi) * 2 + kl;
            const uint32_t swa = (uint32_t)((c16 ^ axr) << 4);
            const uint32_t swb = (uint32_t)((c16 ^ bxr) << 4);
            uint32_t a0[4], a1[4], b0[4], b1[4];
            ldsm_x4(a0, aS + swa);
            ldsm_x4(a1, aS + 16 * 128 + swa);
            ldsm_x4(b0, bS + swb);
            ldsm_x4(b1, bS + 16 * 128 + swb);
            mma16816(acc[0][0], a0, b0[0], b0[2]);
            mma16816(acc[0][1], a0, b0[1], b0[3]);
            mma16816(acc[0][2], a0, b1[0], b1[2]);
            mma16816(acc[0][3], a0, b1[1], b1[3]);
            mma16816(acc[1][0], a1, b0[0], b0[2]);
            mma16816(acc[1][1], a1, b0[1], b0[3]);
            mma16816(acc[1][2], a1, b1[0], b1[2]);
            mma16816(acc[1][3], a1, b1[1], b1[3]);
        }

        if (kc + 2 < G2_NC) {
            const int s2 = (kc + 2) % 3;
            const __half* Ag = Ab + (kc + 2) * BK + (size_t)lrow * KP2 + lcb * 8;
            const __half* Bg = Bb + (kc + 2) * BK + (size_t)lrow * KP2 + lcb * 8;
            const uint32_t rowA = sbase + s2 * ASB + lrow * 128;
            const uint32_t rowB = rowA + BOFFB;
#pragma unroll
            for (int q = 0; q < 2; ++q) {
                const uint32_t sw = (uint32_t)(((lcb + q) ^ lxr) << 4);
                cp_async16(rowA + sw, Ag + q * 8);
                cp_async16(rowB + sw, Bg + q * 8);
            }
        }
        cp_commit();
    }

    cp_wait0();
    __syncthreads();

    float* sC = (float*)smem;
    const int rr = lane >> 2;
    const int cc0 = wn * 32 + (lane & 3) * 2;

    if (grp == 1) {
#pragma unroll
        for (int mt = 0; mt < 2; ++mt)
#pragma unroll
            for (int j = 0; j < 4; ++j) {
                const int r0 = wm * 32 + rr + mt * 16;
                const int c  = cc0 + j * 8;
                float2 v0; v0.x = acc[mt][j][0]; v0.y = acc[mt][j][1];
                float2 v1; v1.x = acc[mt][j][2]; v1.y = acc[mt][j][3];
                *(float2*)(sC + r0 * SDP + c)       = v0;
                *(float2*)(sC + (r0 + 8) * SDP + c) = v1;
            }
    }
    __syncthreads();
    if (grp == 0) {
#pragma unroll
        for (int mt = 0; mt < 2; ++mt)
#pragma unroll
            for (int j = 0; j < 4; ++j) {
                const int r0 = wm * 32 + rr + mt * 16;
                const int c  = cc0 + j * 8;
                float2 p0 = *(float2*)(sC + r0 * SDP + c);
                float2 p1 = *(float2*)(sC + (r0 + 8) * SDP + c);
                p0.x += acc[mt][j][0]; p0.y += acc[mt][j][1];
                p1.x += acc[mt][j][2]; p1.y += acc[mt][j][3];
                *(float2*)(sC + r0 * SDP + c)       = p0;
                *(float2*)(sC + (r0 + 8) * SDP + c) = p1;
            }
    }
    __syncthreads();

    const float bv0 = bias[0], bv1 = bias[1];
    {
        const int r  = tid >> 2;
        const int cb = (tid & 3) * 16;
        float* dbase = outp + ((size_t)(bz * SEQ + m0 + r)) * NJC + n0;
#pragma unroll
        for (int e = 0; e < 8; ++e) {
            const int col = cb + e * 2;
            float2 v;
            v.x = sC[r * SDP + col] + bv0;
            v.y = sC[r * SDP + col + 1] + bv1;
            *(float2*)(dbase + col) = v;
        }
    }
    if (it != jt) {
        const int jl = tid >> 3;
        const int ql = tid & 7;
        const int j  = jt * 64 + half * 32 + jl;
        float* mbase = outp + ((size_t)(bz * SEQ + j)) * NJC + 2 * m0;
#pragma unroll
        for (int e = 0; e < 8; ++e) {
            const int q = ql + 8 * e;
            float2 s = *(float2*)(sC + q * SDP + 2 * jl);
            float2 v;
            v.x = s.x + bv0;
            v.y = s.y + bv1;
            *(float2*)(mbase + 2 * q) = v;
        }
    }
}

// ---------------------------------------------------------------------------
extern "C" void kernel_launch(void* const* d_in, const int* in_sizes, int n_in,
                              void* d_out, int out_size)
{
    const float* x  = (const float*)d_in[0];   // [4, 512, 1024]
    const float* W1 = (const float*)d_in[1];   // [256, 1024]
    const float* b1 = (const float*)d_in[2];   // [256]
    const float* W2 = (const float*)d_in[3];   // [2, 256]
    const float* b2 = (const float*)d_in[4];   // [2]
    float* out = (float*)d_out;                // [4, 512, 512, 2]

    // Prep: fp32 -> fp16 convert (8 floats/thread, MLP=2, 16B stores)
    split_xw<<<(NX8 + NW8) / 256, 256>>>(x, W1);

    // Stage 1 GEMM (full K=1024, fused o/A'/B' epilogue): grid 128 CTAs
    gemm1_kernel<<<dim3(HDIM / 64, MTOT / 64), 256, SMEM_SZ>>>(W2, b1);

    // Stage 2 GEMM (triangular): 36 pairs x 2 jc-halves x 4 batches = 288 CTAs
    gemm2_kernel<<<dim3(2, 36, BNUM), 256, SMEM_SZ>>>(b2, out);
}